// round 15
// baseline (speedup 1.0000x reference)
#include <cuda_runtime.h>
#include <math.h>

#define NMAX  100000
#define EMAX  1600000
#define F_IN  500
#define F_HID 64
#define F_OUT 40
#define CAP   128          // bucket capacity per destination (Poisson(16) -> P(overflow)<1e-80)

// ---------------- scratch (no allocations allowed) ----------------
__device__ float g_xw1[(size_t)NMAX * F_HID];   // X @ W1
__device__ float g_xw2[(size_t)NMAX * F_OUT];   // relu(agg1+b1) @ W2
__device__ float g_dinv[NMAX];                  // rsqrt(1+deg)
__device__ float g_nrm[(size_t)NMAX * CAP];     // cached dinv[src] per bucket slot
__device__ int   g_cnt [NMAX];                  // in-degree (excl. self loop)
__device__ int   g_bucket[(size_t)NMAX * CAP];  // src ids grouped by dst (slots >= cnt stay 0)
__device__ int   g_is64;

// ---------------- init: dtype detect + zero counts ----------------
__global__ void k_init(const unsigned int* __restrict__ e, int N) {
    int i = blockIdx.x * blockDim.x + threadIdx.x;
    if (i < N) g_cnt[i] = 0;
    if (i == 0) {
        int is64 = 1;
        for (int j = 0; j < 64; j++)
            if (e[2 * j + 1] != 0u) { is64 = 0; break; }
        g_is64 = is64;
    }
}

// ---------------- build bucketed CSR (2 edges/thread, vector loads) -----------
__global__ void k_build(const void* __restrict__ e, int E) {
    int i = (blockIdx.x * blockDim.x + threadIdx.x) * 2;
    if (i >= E) return;
    bool two = (i + 1 < E);
    bool al  = ((E & 1) == 0);
    int s0, d0, s1 = 0, d1 = 0;
    if (g_is64) {
        const long long* p = (const long long*)e;
        if (al) {
            longlong2 sp = *(const longlong2*)(p + i);
            longlong2 dp = *(const longlong2*)(p + E + i);
            s0 = (int)sp.x; s1 = (int)sp.y;
            d0 = (int)dp.x; d1 = (int)dp.y;
        } else {
            s0 = (int)p[i];     d0 = (int)p[E + i];
            if (two) { s1 = (int)p[i + 1]; d1 = (int)p[E + i + 1]; }
        }
    } else {
        const int* p = (const int*)e;
        if (al) {
            int2 sp = *(const int2*)(p + i);
            int2 dp = *(const int2*)(p + E + i);
            s0 = sp.x; s1 = sp.y;
            d0 = dp.x; d1 = dp.y;
        } else {
            s0 = p[i];     d0 = p[E + i];
            if (two) { s1 = p[i + 1]; d1 = p[E + i + 1]; }
        }
    }
    int c0 = atomicAdd(&g_cnt[d0], 1);
    if (c0 < CAP) g_bucket[(size_t)d0 * CAP + c0] = s0;
    if (two) {
        int c1 = atomicAdd(&g_cnt[d1], 1);
        if (c1 < CAP) g_bucket[(size_t)d1 * CAP + c1] = s1;
    }
}

// ---------------- tf32 helpers ----------------
__device__ __forceinline__ float to_tf32(float x) {
    float y;
    asm("cvt.rna.tf32.f32 %0, %1;" : "=f"(y) : "f"(x));
    return y;
}
__device__ __forceinline__ void mma_tf32(float* c, const unsigned* a, const unsigned* b) {
    asm volatile(
        "mma.sync.aligned.m16n8k8.row.col.f32.tf32.tf32.f32 "
        "{%0,%1,%2,%3}, {%4,%5,%6,%7}, {%8,%9}, {%0,%1,%2,%3};"
        : "+f"(c[0]), "+f"(c[1]), "+f"(c[2]), "+f"(c[3])
        : "r"(a[0]), "r"(a[1]), "r"(a[2]), "r"(a[3]), "r"(b[0]), "r"(b[1]));
}

// ---- GEMM1 (tf32 MMA, double-buffered smem, 1 sync/tile) + dinv prologue -----
__global__ void __launch_bounds__(256) k_gemm1(const float* __restrict__ X,
                                               const float* __restrict__ W, int N) {
    __shared__ float sX[2][16][136];
    __shared__ float sW[2][16][72];
    int tid  = threadIdx.x;
    int lane = tid & 31, wid = tid >> 5;
    int warpM = wid >> 1, warpN = wid & 1;
    int gid = lane >> 2, tig = lane & 3;
    int row0 = blockIdx.x * 128;

    if (tid < 128) {
        int n = row0 + tid;
        if (n < N) g_dinv[n] = rsqrtf(1.0f + (float)g_cnt[n]);
    }

    float acc[2][4][4] = {};
    int mA0 = tid >> 2,          c4A0 = tid & 3;
    int mA1 = (tid + 256) >> 2,  c4A1 = (tid + 256) & 3;
    int rB  = tid >> 4,          c4B  = tid & 15;

    float4 pX0, pX1, pW;
    #define LOAD_TILE(k0)                                                        \
        {                                                                        \
            int gr0 = row0 + mA0, gc0 = (k0) + c4A0 * 4;                         \
            pX0 = (gr0 < N && gc0 + 3 < F_IN)                                    \
                ? *(const float4*)(X + (size_t)gr0 * F_IN + gc0)                 \
                : make_float4(0.f, 0.f, 0.f, 0.f);                               \
            int gr1 = row0 + mA1, gc1 = (k0) + c4A1 * 4;                         \
            pX1 = (gr1 < N && gc1 + 3 < F_IN)                                    \
                ? *(const float4*)(X + (size_t)gr1 * F_IN + gc1)                 \
                : make_float4(0.f, 0.f, 0.f, 0.f);                               \
            int gk = (k0) + rB;                                                  \
            pW = (gk < F_IN)                                                     \
                ? *(const float4*)(W + (size_t)gk * F_HID + c4B * 4)             \
                : make_float4(0.f, 0.f, 0.f, 0.f);                               \
        }
    #define STORE_TILE(b)                                                        \
        {                                                                        \
            sX[b][c4A0 * 4 + 0][mA0] = to_tf32(pX0.x);                           \
            sX[b][c4A0 * 4 + 1][mA0] = to_tf32(pX0.y);                           \
            sX[b][c4A0 * 4 + 2][mA0] = to_tf32(pX0.z);                           \
            sX[b][c4A0 * 4 + 3][mA0] = to_tf32(pX0.w);                           \
            sX[b][c4A1 * 4 + 0][mA1] = to_tf32(pX1.x);                           \
            sX[b][c4A1 * 4 + 1][mA1] = to_tf32(pX1.y);                           \
            sX[b][c4A1 * 4 + 2][mA1] = to_tf32(pX1.z);                           \
            sX[b][c4A1 * 4 + 3][mA1] = to_tf32(pX1.w);                           \
            sW[b][rB][c4B * 4 + 0] = to_tf32(pW.x);                              \
            sW[b][rB][c4B * 4 + 1] = to_tf32(pW.y);                              \
            sW[b][rB][c4B * 4 + 2] = to_tf32(pW.z);                              \
            sW[b][rB][c4B * 4 + 3] = to_tf32(pW.w);                              \
        }

    LOAD_TILE(0);
    STORE_TILE(0);
    __syncthreads();
    int buf = 0;
    for (int k0 = 0; k0 < 512; k0 += 16) {
        bool more = (k0 + 16 < 512);
        if (more) LOAD_TILE(k0 + 16);
        #pragma unroll
        for (int ks = 0; ks < 2; ks++) {
            int kb = ks * 8;
            unsigned a[2][4], b[4][2];
            #pragma unroll
            for (int r = 0; r < 2; r++) {
                int rb = warpM * 32 + r * 16;
                a[r][0] = __float_as_uint(sX[buf][kb + tig    ][rb + gid    ]);
                a[r][1] = __float_as_uint(sX[buf][kb + tig    ][rb + 8 + gid]);
                a[r][2] = __float_as_uint(sX[buf][kb + tig + 4][rb + gid    ]);
                a[r][3] = __float_as_uint(sX[buf][kb + tig + 4][rb + 8 + gid]);
            }
            #pragma unroll
            for (int cc = 0; cc < 4; cc++) {
                int cb = warpN * 32 + cc * 8;
                b[cc][0] = __float_as_uint(sW[buf][kb + tig    ][cb + gid]);
                b[cc][1] = __float_as_uint(sW[buf][kb + tig + 4][cb + gid]);
            }
            #pragma unroll
            for (int r = 0; r < 2; r++)
                #pragma unroll
                for (int cc = 0; cc < 4; cc++)
                    mma_tf32(acc[r][cc], a[r], b[cc]);
        }
        if (more) {
            STORE_TILE(buf ^ 1);
            buf ^= 1;
            __syncthreads();
        }
    }
    #pragma unroll
    for (int r = 0; r < 2; r++) {
        int gr = row0 + warpM * 32 + r * 16 + gid;
        #pragma unroll
        for (int cc = 0; cc < 4; cc++) {
            int gc = warpN * 32 + cc * 8 + 2 * tig;
            if (gr < N)
                *(float2*)(g_xw1 + (size_t)gr * F_HID + gc) =
                    make_float2(acc[r][cc][0], acc[r][cc][1]);
            if (gr + 8 < N)
                *(float2*)(g_xw1 + (size_t)(gr + 8) * F_HID + gc) =
                    make_float2(acc[r][cc][2], acc[r][cc][3]);
        }
    }
    #undef LOAD_TILE
    #undef STORE_TILE
}

// ------ layer-1 aggregation (warp/node, sw-pipelined gather) + MMA GEMM2 ------
// block = 512 threads = 16 warps = 16 nodes. 2 blocks/SM (reg budget for prefetch).
__global__ void __launch_bounds__(512, 2) k_agg1(const float* __restrict__ W2,
                                                 const float* __restrict__ b1, int N) {
    __shared__ float sW[64][41];    // W2 as tf32, k-major
    __shared__ float sH[16][68];    // relu(h+b1) as tf32, node-major
    int tid  = threadIdx.x;
    int wip  = tid >> 5;
    int lane = tid & 31;
    int half = lane >> 4;
    int li   = lane & 15;
    int gid  = lane >> 2, tig = lane & 3;
    int w = blockIdx.x * 16 + wip;

    for (int i = tid; i < 64 * 40; i += 512) sW[i / 40][i % 40] = to_tf32(W2[i]);

    float4 aA = make_float4(0.f, 0.f, 0.f, 0.f), aB = aA;
    if (w < N) {
        float dd  = g_dinv[w];
        int   cnt = min(g_cnt[w], CAP);
        const int* bkt = g_bucket + (size_t)w * CAP;
        float*     nrm = g_nrm   + (size_t)w * CAP;
        if (half == 0) {
            float4 xd = *(const float4*)(g_xw1 + (size_t)w * F_HID + li * 4);
            float s2 = dd * dd;
            aA.x = xd.x * s2; aA.y = xd.y * s2; aA.z = xd.z * s2; aA.w = xd.w * s2;
        }
        for (int i0 = 0; i0 < cnt; i0 += 32) {
            int idx = i0 + lane;
            int   sv = bkt[idx];
            float nv = (idx < cnt) ? g_dinv[sv] : 0.f;
            nrm[idx] = nv;
            int m  = min(cnt - i0, 32);
            int mr = (m + 3) & ~3;
            // prologue: fetch first pair
            int   sA = __shfl_sync(0xffffffffu, sv, half);
            float nA = dd * __shfl_sync(0xffffffffu, nv, half);
            int   sB = __shfl_sync(0xffffffffu, sv, 2 + half);
            float nB = dd * __shfl_sync(0xffffffffu, nv, 2 + half);
            float4 xA = *(const float4*)(g_xw1 + (size_t)sA * F_HID + li * 4);
            float4 xB = *(const float4*)(g_xw1 + (size_t)sB * F_HID + li * 4);
            for (int j = 0; j < mr; j += 4) {
                bool morep = (j + 4 < mr);       // warp-uniform
                float4 yA, yB; float mA = 0.f, mB = 0.f;
                if (morep) {                     // prefetch next pair BEFORE FMAs
                    int   tA = __shfl_sync(0xffffffffu, sv, j + 4 + half);
                    mA = dd * __shfl_sync(0xffffffffu, nv, j + 4 + half);
                    int   tB = __shfl_sync(0xffffffffu, sv, j + 6 + half);
                    mB = dd * __shfl_sync(0xffffffffu, nv, j + 6 + half);
                    yA = *(const float4*)(g_xw1 + (size_t)tA * F_HID + li * 4);
                    yB = *(const float4*)(g_xw1 + (size_t)tB * F_HID + li * 4);
                }
                aA.x += xA.x * nA; aA.y += xA.y * nA;
                aA.z += xA.z * nA; aA.w += xA.w * nA;
                aB.x += xB.x * nB; aB.y += xB.y * nB;
                aB.z += xB.z * nB; aB.w += xB.w * nB;
                if (morep) { xA = yA; nA = mA; xB = yB; nB = mB; }
            }
        }
    }
    aA.x += aB.x; aA.y += aB.y; aA.z += aB.z; aA.w += aB.w;
    aA.x += __shfl_xor_sync(0xffffffffu, aA.x, 16);
    aA.y += __shfl_xor_sync(0xffffffffu, aA.y, 16);
    aA.z += __shfl_xor_sync(0xffffffffu, aA.z, 16);
    aA.w += __shfl_xor_sync(0xffffffffu, aA.w, 16);
    if (half == 0) {
        float4 bv = *(const float4*)(b1 + li * 4);
        sH[wip][li * 4 + 0] = to_tf32(fmaxf(aA.x + bv.x, 0.f));
        sH[wip][li * 4 + 1] = to_tf32(fmaxf(aA.y + bv.y, 0.f));
        sH[wip][li * 4 + 2] = to_tf32(fmaxf(aA.z + bv.z, 0.f));
        sH[wip][li * 4 + 3] = to_tf32(fmaxf(aA.w + bv.w, 0.f));
    }
    __syncthreads();
    if (wip < 5) {
        int n0 = wip * 8;
        float c[4] = {0.f, 0.f, 0.f, 0.f};
        unsigned a[4], b[2];
        #pragma unroll
        for (int k0 = 0; k0 < 64; k0 += 8) {
            a[0] = __float_as_uint(sH[gid    ][k0 + tig    ]);
            a[1] = __float_as_uint(sH[gid + 8][k0 + tig    ]);
            a[2] = __float_as_uint(sH[gid    ][k0 + tig + 4]);
            a[3] = __float_as_uint(sH[gid + 8][k0 + tig + 4]);
            b[0] = __float_as_uint(sW[k0 + tig    ][n0 + gid]);
            b[1] = __float_as_uint(sW[k0 + tig + 4][n0 + gid]);
            mma_tf32(c, a, b);
        }
        int node0 = blockIdx.x * 16 + gid;
        if (node0 < N)
            *(float2*)(g_xw2 + (size_t)node0 * F_OUT + n0 + 2 * tig) =
                make_float2(c[0], c[1]);
        if (node0 + 8 < N)
            *(float2*)(g_xw2 + (size_t)(node0 + 8) * F_OUT + n0 + 2 * tig) =
                make_float2(c[2], c[3]);
    }
}

// ------ layer-2 aggregation (sw-pipelined, cached norms) + log-softmax --------
__global__ void __launch_bounds__(512, 2) k_agg2(float* __restrict__ out,
                                                 float* __restrict__ logits,
                                                 const float* __restrict__ b2, int N) {
    int tid  = threadIdx.x;
    int wip  = tid >> 5;
    int lane = tid & 31;
    int half = lane >> 4;
    int li   = lane & 15;
    bool act = li < 10;
    int w = blockIdx.x * 16 + wip;

    float4 aA = make_float4(0.f, 0.f, 0.f, 0.f), aB = aA;
    if (w < N) {
        float dd  = g_dinv[w];
        int   cnt = min(g_cnt[w], CAP);
        const int*   bkt = g_bucket + (size_t)w * CAP;
        const float* nrm = g_nrm   + (size_t)w * CAP;
        if (half == 0 && act) {
            float4 xd = *(const float4*)(g_xw2 + (size_t)w * F_OUT + li * 4);
            float s2 = dd * dd;
            aA.x = xd.x * s2; aA.y = xd.y * s2; aA.z = xd.z * s2; aA.w = xd.w * s2;
        }
        for (int i0 = 0; i0 < cnt; i0 += 32) {
            int idx = i0 + lane;
            int   sv = bkt[idx];
            float nv = nrm[idx];
            int m  = min(cnt - i0, 32);
            int mr = (m + 3) & ~3;
            int   sA = __shfl_sync(0xffffffffu, sv, half);
            float nA = dd * __shfl_sync(0xffffffffu, nv, half);
            int   sB = __shfl_sync(0xffffffffu, sv, 2 + half);
            float nB = dd * __shfl_sync(0xffffffffu, nv, 2 + half);
            float4 xA = make_float4(0.f, 0.f, 0.f, 0.f), xB = xA;
            if (act) {
                xA = *(const float4*)(g_xw2 + (size_t)sA * F_OUT + li * 4);
                xB = *(const float4*)(g_xw2 + (size_t)sB * F_OUT + li * 4);
            }
            for (int j = 0; j < mr; j += 4) {
                bool morep = (j + 4 < mr);
                float4 yA = make_float4(0.f, 0.f, 0.f, 0.f), yB = yA;
                float mA = 0.f, mB = 0.f;
                if (morep) {
                    int   tA = __shfl_sync(0xffffffffu, sv, j + 4 + half);
                    mA = dd * __shfl_sync(0xffffffffu, nv, j + 4 + half);
                    int   tB = __shfl_sync(0xffffffffu, sv, j + 6 + half);
                    mB = dd * __shfl_sync(0xffffffffu, nv, j + 6 + half);
                    if (act) {
                        yA = *(const float4*)(g_xw2 + (size_t)tA * F_OUT + li * 4);
                        yB = *(const float4*)(g_xw2 + (size_t)tB * F_OUT + li * 4);
                    }
                }
                aA.x += xA.x * nA; aA.y += xA.y * nA;
                aA.z += xA.z * nA; aA.w += xA.w * nA;
                aB.x += xB.x * nB; aB.y += xB.y * nB;
                aB.z += xB.z * nB; aB.w += xB.w * nB;
                if (morep) { xA = yA; nA = mA; xB = yB; nB = mB; }
            }
        }
    }
    aA.x += aB.x; aA.y += aB.y; aA.z += aB.z; aA.w += aB.w;
    aA.x += __shfl_xor_sync(0xffffffffu, aA.x, 16);
    aA.y += __shfl_xor_sync(0xffffffffu, aA.y, 16);
    aA.z += __shfl_xor_sync(0xffffffffu, aA.z, 16);
    aA.w += __shfl_xor_sync(0xffffffffu, aA.w, 16);

    float4 l4 = make_float4(-INFINITY, -INFINITY, -INFINITY, -INFINITY);
    bool fin = (w < N) && (half == 0) && act;
    if (fin) {
        float4 bv = *(const float4*)(b2 + li * 4);
        l4 = make_float4(aA.x + bv.x, aA.y + bv.y, aA.z + bv.z, aA.w + bv.w);
        *(float4*)(logits + (size_t)w * F_OUT + li * 4) = l4;
    }
    float mx = fmaxf(fmaxf(l4.x, l4.y), fmaxf(l4.z, l4.w));
    #pragma unroll
    for (int o = 16; o; o >>= 1) mx = fmaxf(mx, __shfl_xor_sync(0xffffffffu, mx, o));
    float es = fin ? (expf(l4.x - mx) + expf(l4.y - mx) + expf(l4.z - mx) + expf(l4.w - mx)) : 0.f;
    #pragma unroll
    for (int o = 16; o; o >>= 1) es += __shfl_xor_sync(0xffffffffu, es, o);
    float lse = mx + logf(es);
    if (fin)
        *(float4*)(out + (size_t)w * F_OUT + li * 4) =
            make_float4(l4.x - lse, l4.y - lse, l4.z - lse, l4.w - lse);
}

// ---------------- launch ----------------
extern "C" void kernel_launch(void* const* d_in, const int* in_sizes, int n_in,
                              void* d_out, int out_size) {
    const float* x  = (const float*)d_in[0];
    const void*  ei = d_in[1];
    const float* W1 = (const float*)d_in[2];
    const float* b1 = (const float*)d_in[3];
    const float* W2 = (const float*)d_in[4];
    const float* b2 = (const float*)d_in[5];
    int N = in_sizes[0] / F_IN;
    int E = in_sizes[1] / 2;
    if (N > NMAX) N = NMAX;
    if (E > EMAX) E = EMAX;

    float* out_lsm = (float*)d_out;
    float* logits  = out_lsm + (size_t)N * F_OUT;

    k_init  <<<(N + 255) / 256, 256>>>((const unsigned int*)ei, N);
    k_build <<<(E + 511) / 512, 256>>>(ei, E);
    k_gemm1 <<<(N + 127) / 128, 256>>>(x, W1, N);
    k_agg1  <<<(N + 15) / 16, 512>>>(W2, b1, N);
    k_agg2  <<<(N + 15) / 16, 512>>>(out_lsm, logits, b2, N);
}

// round 16
// speedup vs baseline: 1.1902x; 1.1902x over previous
#include <cuda_runtime.h>
#include <math.h>

#define NMAX  100000
#define EMAX  1600000
#define F_IN  500
#define F_HID 64
#define F_OUT 40
#define CAP   128          // bucket capacity per destination (Poisson(16) -> P(overflow)<1e-80)

// ---------------- scratch (no allocations allowed) ----------------
__device__ float g_xw1[(size_t)NMAX * F_HID];   // (X @ W1) * dinv[row]  (pre-scaled)
__device__ float g_xw2[(size_t)NMAX * F_OUT];   // (relu(h+b1) @ W2) * dinv[row]
__device__ float g_dinv[NMAX];                  // rsqrt(1+deg)
__device__ int   g_cnt [NMAX];                  // in-degree (excl. self loop)
__device__ int   g_bucket[(size_t)NMAX * CAP];  // src ids grouped by dst
__device__ int   g_is64;

// ---------------- init: dtype detect + zero counts ----------------
__global__ void k_init(const unsigned int* __restrict__ e, int N) {
    int i = blockIdx.x * blockDim.x + threadIdx.x;
    if (i < N) g_cnt[i] = 0;
    if (i == 0) {
        int is64 = 1;
        for (int j = 0; j < 64; j++)
            if (e[2 * j + 1] != 0u) { is64 = 0; break; }
        g_is64 = is64;
    }
}

// ---------------- build bucketed CSR (2 edges/thread, vector loads) -----------
__global__ void k_build(const void* __restrict__ e, int E) {
    int i = (blockIdx.x * blockDim.x + threadIdx.x) * 2;
    if (i >= E) return;
    bool two = (i + 1 < E);
    bool al  = ((E & 1) == 0);
    int s0, d0, s1 = 0, d1 = 0;
    if (g_is64) {
        const long long* p = (const long long*)e;
        if (al) {
            longlong2 sp = *(const longlong2*)(p + i);
            longlong2 dp = *(const longlong2*)(p + E + i);
            s0 = (int)sp.x; s1 = (int)sp.y;
            d0 = (int)dp.x; d1 = (int)dp.y;
        } else {
            s0 = (int)p[i];     d0 = (int)p[E + i];
            if (two) { s1 = (int)p[i + 1]; d1 = (int)p[E + i + 1]; }
        }
    } else {
        const int* p = (const int*)e;
        if (al) {
            int2 sp = *(const int2*)(p + i);
            int2 dp = *(const int2*)(p + E + i);
            s0 = sp.x; s1 = sp.y;
            d0 = dp.x; d1 = dp.y;
        } else {
            s0 = p[i];     d0 = p[E + i];
            if (two) { s1 = p[i + 1]; d1 = p[E + i + 1]; }
        }
    }
    int c0 = atomicAdd(&g_cnt[d0], 1);
    if (c0 < CAP) g_bucket[(size_t)d0 * CAP + c0] = s0;
    if (two) {
        int c1 = atomicAdd(&g_cnt[d1], 1);
        if (c1 < CAP) g_bucket[(size_t)d1 * CAP + c1] = s1;
    }
}

// ---------------- tf32 helpers ----------------
__device__ __forceinline__ float to_tf32(float x) {
    float y;
    asm("cvt.rna.tf32.f32 %0, %1;" : "=f"(y) : "f"(x));
    return y;
}
__device__ __forceinline__ void mma_tf32(float* c, const unsigned* a, const unsigned* b) {
    asm volatile(
        "mma.sync.aligned.m16n8k8.row.col.f32.tf32.tf32.f32 "
        "{%0,%1,%2,%3}, {%4,%5,%6,%7}, {%8,%9}, {%0,%1,%2,%3};"
        : "+f"(c[0]), "+f"(c[1]), "+f"(c[2]), "+f"(c[3])
        : "r"(a[0]), "r"(a[1]), "r"(a[2]), "r"(a[3]), "r"(b[0]), "r"(b[1]));
}

// ---- GEMM1 (tf32 MMA, double-buffered) + dinv prologue + PRE-SCALED writeback -
__global__ void __launch_bounds__(256) k_gemm1(const float* __restrict__ X,
                                               const float* __restrict__ W, int N) {
    __shared__ float sX[2][16][136];
    __shared__ float sW[2][16][72];
    int tid  = threadIdx.x;
    int lane = tid & 31, wid = tid >> 5;
    int warpM = wid >> 1, warpN = wid & 1;
    int gid = lane >> 2, tig = lane & 3;
    int row0 = blockIdx.x * 128;

    if (tid < 128) {
        int n = row0 + tid;
        if (n < N) g_dinv[n] = rsqrtf(1.0f + (float)g_cnt[n]);
    }

    float acc[2][4][4] = {};
    int mA0 = tid >> 2,          c4A0 = tid & 3;
    int mA1 = (tid + 256) >> 2,  c4A1 = (tid + 256) & 3;
    int rB  = tid >> 4,          c4B  = tid & 15;

    float4 pX0, pX1, pW;
    #define LOAD_TILE(k0)                                                        \
        {                                                                        \
            int gr0 = row0 + mA0, gc0 = (k0) + c4A0 * 4;                         \
            pX0 = (gr0 < N && gc0 + 3 < F_IN)                                    \
                ? *(const float4*)(X + (size_t)gr0 * F_IN + gc0)                 \
                : make_float4(0.f, 0.f, 0.f, 0.f);                               \
            int gr1 = row0 + mA1, gc1 = (k0) + c4A1 * 4;                         \
            pX1 = (gr1 < N && gc1 + 3 < F_IN)                                    \
                ? *(const float4*)(X + (size_t)gr1 * F_IN + gc1)                 \
                : make_float4(0.f, 0.f, 0.f, 0.f);                               \
            int gk = (k0) + rB;                                                  \
            pW = (gk < F_IN)                                                     \
                ? *(const float4*)(W + (size_t)gk * F_HID + c4B * 4)             \
                : make_float4(0.f, 0.f, 0.f, 0.f);                               \
        }
    #define STORE_TILE(b)                                                        \
        {                                                                        \
            sX[b][c4A0 * 4 + 0][mA0] = to_tf32(pX0.x);                           \
            sX[b][c4A0 * 4 + 1][mA0] = to_tf32(pX0.y);                           \
            sX[b][c4A0 * 4 + 2][mA0] = to_tf32(pX0.z);                           \
            sX[b][c4A0 * 4 + 3][mA0] = to_tf32(pX0.w);                           \
            sX[b][c4A1 * 4 + 0][mA1] = to_tf32(pX1.x);                           \
            sX[b][c4A1 * 4 + 1][mA1] = to_tf32(pX1.y);                           \
            sX[b][c4A1 * 4 + 2][mA1] = to_tf32(pX1.z);                           \
            sX[b][c4A1 * 4 + 3][mA1] = to_tf32(pX1.w);                           \
            sW[b][rB][c4B * 4 + 0] = to_tf32(pW.x);                              \
            sW[b][rB][c4B * 4 + 1] = to_tf32(pW.y);                              \
            sW[b][rB][c4B * 4 + 2] = to_tf32(pW.z);                              \
            sW[b][rB][c4B * 4 + 3] = to_tf32(pW.w);                              \
        }

    LOAD_TILE(0);
    STORE_TILE(0);
    __syncthreads();
    int buf = 0;
    for (int k0 = 0; k0 < 512; k0 += 16) {
        bool more = (k0 + 16 < 512);
        if (more) LOAD_TILE(k0 + 16);
        #pragma unroll
        for (int ks = 0; ks < 2; ks++) {
            int kb = ks * 8;
            unsigned a[2][4], b[4][2];
            #pragma unroll
            for (int r = 0; r < 2; r++) {
                int rb = warpM * 32 + r * 16;
                a[r][0] = __float_as_uint(sX[buf][kb + tig    ][rb + gid    ]);
                a[r][1] = __float_as_uint(sX[buf][kb + tig    ][rb + 8 + gid]);
                a[r][2] = __float_as_uint(sX[buf][kb + tig + 4][rb + gid    ]);
                a[r][3] = __float_as_uint(sX[buf][kb + tig + 4][rb + 8 + gid]);
            }
            #pragma unroll
            for (int cc = 0; cc < 4; cc++) {
                int cb = warpN * 32 + cc * 8;
                b[cc][0] = __float_as_uint(sW[buf][kb + tig    ][cb + gid]);
                b[cc][1] = __float_as_uint(sW[buf][kb + tig + 4][cb + gid]);
            }
            #pragma unroll
            for (int r = 0; r < 2; r++)
                #pragma unroll
                for (int cc = 0; cc < 4; cc++)
                    mma_tf32(acc[r][cc], a[r], b[cc]);
        }
        if (more) {
            STORE_TILE(buf ^ 1);
            buf ^= 1;
            __syncthreads();
        }
    }
    #pragma unroll
    for (int r = 0; r < 2; r++) {
        int gr = row0 + warpM * 32 + r * 16 + gid;
        float dv0 = (gr < N)     ? g_dinv[gr]     : 0.f;   // written by this block's prologue
        float dv1 = (gr + 8 < N) ? g_dinv[gr + 8] : 0.f;
        #pragma unroll
        for (int cc = 0; cc < 4; cc++) {
            int gc = warpN * 32 + cc * 8 + 2 * tig;
            if (gr < N)
                *(float2*)(g_xw1 + (size_t)gr * F_HID + gc) =
                    make_float2(acc[r][cc][0] * dv0, acc[r][cc][1] * dv0);
            if (gr + 8 < N)
                *(float2*)(g_xw1 + (size_t)(gr + 8) * F_HID + gc) =
                    make_float2(acc[r][cc][2] * dv1, acc[r][cc][3] * dv1);
        }
    }
    #undef LOAD_TILE
    #undef STORE_TILE
}

// ------ layer-1 aggregation (warp/node, PURE-ADD gather) + MMA GEMM2 ----------
// xw1 rows pre-scaled by dinv[src] => no per-source norms. 3 blocks/SM.
__global__ void __launch_bounds__(512, 3) k_agg1(const float* __restrict__ W2,
                                                 const float* __restrict__ b1, int N) {
    __shared__ float sW[64][41];    // W2 as tf32, k-major
    __shared__ float sH[16][68];    // relu(h+b1) as tf32, node-major
    int tid  = threadIdx.x;
    int wip  = tid >> 5;
    int lane = tid & 31;
    int half = lane >> 4;
    int li   = lane & 15;
    int gid  = lane >> 2, tig = lane & 3;
    int w = blockIdx.x * 16 + wip;

    for (int i = tid; i < 64 * 40; i += 512) sW[i / 40][i % 40] = to_tf32(W2[i]);

    float dd = 0.f;
    float4 aA = make_float4(0.f, 0.f, 0.f, 0.f), aB = aA;
    if (w < N) {
        dd = g_dinv[w];
        int cnt = min(g_cnt[w], CAP);
        const int* bkt = g_bucket + (size_t)w * CAP;
        if (half == 0)              // self term: xw1s[w] (already scaled by dinv[w])
            aA = *(const float4*)(g_xw1 + (size_t)w * F_HID + li * 4);
        for (int i0 = 0; i0 < cnt; i0 += 32) {
            int sv = bkt[i0 + lane];
            int m  = min(cnt - i0, 32);
            int m4 = m & ~3;
            int j = 0;
            for (; j < m4; j += 4) {
                int sA = __shfl_sync(0xffffffffu, sv, j + half);
                int sB = __shfl_sync(0xffffffffu, sv, j + 2 + half);
                float4 xA = *(const float4*)(g_xw1 + (size_t)sA * F_HID + li * 4);
                float4 xB = *(const float4*)(g_xw1 + (size_t)sB * F_HID + li * 4);
                aA.x += xA.x; aA.y += xA.y; aA.z += xA.z; aA.w += xA.w;
                aB.x += xB.x; aB.y += xB.y; aB.z += xB.z; aB.w += xB.w;
            }
            for (; j < m; j++) {    // 0-3 tail sources, half0 accumulates
                int sC = __shfl_sync(0xffffffffu, sv, j);
                float4 xC = *(const float4*)(g_xw1 + (size_t)sC * F_HID + li * 4);
                if (half == 0) {
                    aA.x += xC.x; aA.y += xC.y; aA.z += xC.z; aA.w += xC.w;
                }
            }
        }
    }
    aA.x += aB.x; aA.y += aB.y; aA.z += aB.z; aA.w += aB.w;
    aA.x += __shfl_xor_sync(0xffffffffu, aA.x, 16);
    aA.y += __shfl_xor_sync(0xffffffffu, aA.y, 16);
    aA.z += __shfl_xor_sync(0xffffffffu, aA.z, 16);
    aA.w += __shfl_xor_sync(0xffffffffu, aA.w, 16);
    if (half == 0) {                // h = dd * sum; rows w>=N hold relu(b1) (dd=0)
        float4 bv = *(const float4*)(b1 + li * 4);
        sH[wip][li * 4 + 0] = to_tf32(fmaxf(aA.x * dd + bv.x, 0.f));
        sH[wip][li * 4 + 1] = to_tf32(fmaxf(aA.y * dd + bv.y, 0.f));
        sH[wip][li * 4 + 2] = to_tf32(fmaxf(aA.z * dd + bv.z, 0.f));
        sH[wip][li * 4 + 3] = to_tf32(fmaxf(aA.w * dd + bv.w, 0.f));
    }
    __syncthreads();
    // GEMM2 epilogue via tf32 MMA, writeback PRE-SCALED by dinv[node]
    if (wip < 5) {
        int n0 = wip * 8;
        float c[4] = {0.f, 0.f, 0.f, 0.f};
        unsigned a[4], b[2];
        #pragma unroll
        for (int k0 = 0; k0 < 64; k0 += 8) {
            a[0] = __float_as_uint(sH[gid    ][k0 + tig    ]);
            a[1] = __float_as_uint(sH[gid + 8][k0 + tig    ]);
            a[2] = __float_as_uint(sH[gid    ][k0 + tig + 4]);
            a[3] = __float_as_uint(sH[gid + 8][k0 + tig + 4]);
            b[0] = __float_as_uint(sW[k0 + tig    ][n0 + gid]);
            b[1] = __float_as_uint(sW[k0 + tig + 4][n0 + gid]);
            mma_tf32(c, a, b);
        }
        int node0 = blockIdx.x * 16 + gid;
        if (node0 < N) {
            float dv = g_dinv[node0];
            *(float2*)(g_xw2 + (size_t)node0 * F_OUT + n0 + 2 * tig) =
                make_float2(c[0] * dv, c[1] * dv);
        }
        if (node0 + 8 < N) {
            float dv = g_dinv[node0 + 8];
            *(float2*)(g_xw2 + (size_t)(node0 + 8) * F_OUT + n0 + 2 * tig) =
                make_float2(c[2] * dv, c[3] * dv);
        }
    }
}

// ------ layer-2 aggregation (PURE-ADD gather) + fused log-softmax -------------
__global__ void __launch_bounds__(512, 3) k_agg2(float* __restrict__ out,
                                                 float* __restrict__ logits,
                                                 const float* __restrict__ b2, int N) {
    int tid  = threadIdx.x;
    int wip  = tid >> 5;
    int lane = tid & 31;
    int half = lane >> 4;
    int li   = lane & 15;
    bool act = li < 10;             // 10 float4 = 40 feats per half
    int w = blockIdx.x * 16 + wip;

    float dd = 0.f;
    float4 aA = make_float4(0.f, 0.f, 0.f, 0.f), aB = aA;
    if (w < N) {
        dd = g_dinv[w];
        int cnt = min(g_cnt[w], CAP);
        const int* bkt = g_bucket + (size_t)w * CAP;
        if (half == 0 && act)       // self term (pre-scaled)
            aA = *(const float4*)(g_xw2 + (size_t)w * F_OUT + li * 4);
        for (int i0 = 0; i0 < cnt; i0 += 32) {
            int sv = bkt[i0 + lane];
            int m  = min(cnt - i0, 32);
            int m4 = m & ~3;
            int j = 0;
            for (; j < m4; j += 4) {
                int sA = __shfl_sync(0xffffffffu, sv, j + half);
                int sB = __shfl_sync(0xffffffffu, sv, j + 2 + half);
                if (act) {
                    float4 xA = *(const float4*)(g_xw2 + (size_t)sA * F_OUT + li * 4);
                    float4 xB = *(const float4*)(g_xw2 + (size_t)sB * F_OUT + li * 4);
                    aA.x += xA.x; aA.y += xA.y; aA.z += xA.z; aA.w += xA.w;
                    aB.x += xB.x; aB.y += xB.y; aB.z += xB.z; aB.w += xB.w;
                }
            }
            for (; j < m; j++) {
                int sC = __shfl_sync(0xffffffffu, sv, j);
                if (act && half == 0) {
                    float4 xC = *(const float4*)(g_xw2 + (size_t)sC * F_OUT + li * 4);
                    aA.x += xC.x; aA.y += xC.y; aA.z += xC.z; aA.w += xC.w;
                }
            }
        }
    }
    aA.x += aB.x; aA.y += aB.y; aA.z += aB.z; aA.w += aB.w;
    aA.x += __shfl_xor_sync(0xffffffffu, aA.x, 16);
    aA.y += __shfl_xor_sync(0xffffffffu, aA.y, 16);
    aA.z += __shfl_xor_sync(0xffffffffu, aA.z, 16);
    aA.w += __shfl_xor_sync(0xffffffffu, aA.w, 16);

    float4 l4 = make_float4(-INFINITY, -INFINITY, -INFINITY, -INFINITY);
    bool fin = (w < N) && (half == 0) && act;
    if (fin) {
        float4 bv = *(const float4*)(b2 + li * 4);
        l4 = make_float4(aA.x * dd + bv.x, aA.y * dd + bv.y,
                         aA.z * dd + bv.z, aA.w * dd + bv.w);
        *(float4*)(logits + (size_t)w * F_OUT + li * 4) = l4;
    }
    // warp log-softmax over the 40 logits
    float mx = fmaxf(fmaxf(l4.x, l4.y), fmaxf(l4.z, l4.w));
    #pragma unroll
    for (int o = 16; o; o >>= 1) mx = fmaxf(mx, __shfl_xor_sync(0xffffffffu, mx, o));
    float es = fin ? (expf(l4.x - mx) + expf(l4.y - mx) + expf(l4.z - mx) + expf(l4.w - mx)) : 0.f;
    #pragma unroll
    for (int o = 16; o; o >>= 1) es += __shfl_xor_sync(0xffffffffu, es, o);
    float lse = mx + logf(es);
    if (fin)
        *(float4*)(out + (size_t)w * F_OUT + li * 4) =
            make_float4(l4.x - lse, l4.y - lse, l4.z - lse, l4.w - lse);
}

// ---------------- launch ----------------
extern "C" void kernel_launch(void* const* d_in, const int* in_sizes, int n_in,
                              void* d_out, int out_size) {
    const float* x  = (const float*)d_in[0];
    const void*  ei = d_in[1];
    const float* W1 = (const float*)d_in[2];
    const float* b1 = (const float*)d_in[3];
    const float* W2 = (const float*)d_in[4];
    const float* b2 = (const float*)d_in[5];
    int N = in_sizes[0] / F_IN;
    int E = in_sizes[1] / 2;
    if (N > NMAX) N = NMAX;
    if (E > EMAX) E = EMAX;

    float* out_lsm = (float*)d_out;
    float* logits  = out_lsm + (size_t)N * F_OUT;

    k_init  <<<(N + 255) / 256, 256>>>((const unsigned int*)ei, N);
    k_build <<<(E + 511) / 512, 256>>>(ei, E);
    k_gemm1 <<<(N + 127) / 128, 256>>>(x, W1, N);
    k_agg1  <<<(N + 15) / 16, 512>>>(W2, b1, N);
    k_agg2  <<<(N + 15) / 16, 512>>>(out_lsm, logits, b2, N);
}